// round 13
// baseline (speedup 1.0000x reference)
#include <cuda_runtime.h>
#include <stdint.h>
#include <math.h>

// Problem constants (fixed by the dataset).
#define NN      8192
#define CC      64
#define EMAX    262144
#define PAD     128                 // padded CSR row stride (mean deg 32)
#define TS      (1u << 19)          // hash slots (load factor ~0.5)
#define TMASK   (TS - 1u)
#define LISTCAP 16384
#define GENMAX  0xFFFFFu            // 20-bit generation tag

// Table entry layout: [gen:20 | key:26 | idx:18]. Slot is EMPTY iff its gen
// tag != current g_gen (so the 4 MB table never needs clearing). gen starts
// at 1 (static-zero slots = gen 0 = never valid) and skips 0 on wrap.
__device__ unsigned long long g_table[TS];
__device__ unsigned g_gen = 1;

// ---------------- scratch (static device globals; no allocation) -------------
__device__ int      g_count[NN];          // distinct cells per row (zeroed in epilogue)
__device__ float    g_deg[NN];            // (zeroed in epilogue)
__device__ unsigned g_pos[TS];            // apos recorded by the claimant of a slot
__device__ __align__(16) uint2 g_cw[NN * PAD];   // 8 MB interleaved (col, w)
__device__ float2   g_tx1[NN * 32];
__device__ int      g_nlist;
__device__ uint2    g_list[LISTCAP];      // (slot, edge idx) of duplicate-key inserts

// ---------------- kernels ----------------------------------------------------

// Insert: gen-tagged claim of a cell takes a padded-CSR position and writes
// (col,w) + REDG degree. Duplicate-key edges -> atomicMax (max edge idx =
// last-write-wins) + tiny fix list. Edge dtype detected inline (odd words of
// the first 8 int64 entries are zero; uniform L1-hot loads, ~free).
__global__ void k_insert(const unsigned* __restrict__ ei,
                         const float* __restrict__ ew,
                         const float* __restrict__ adw, int E) {
    int i = blockIdx.x * blockDim.x + threadIdx.x;
    if (i >= E) return;
    bool is64 = ((ei[1] | ei[3] | ei[5] | ei[7] |
                  ei[9] | ei[11] | ei[13] | ei[15]) == 0u);
    unsigned row, col;
    if (is64) {                                   // coalesced 8B loads
        row = ((const uint2*)ei)[i].x;
        col = ((const uint2*)ei)[E + i].x;
    } else {
        row = ei[i];
        col = ei[E + i];
    }
    float sig = 1.f / (1.f + expf(-adw[0]));
    float aw  = ew[i] * sig;
    unsigned gen = g_gen;
    unsigned key = (row << 13) | col;                          // 26 bits
    unsigned long long tagkey =
        ((unsigned long long)gen << 44) | ((unsigned long long)key << 18);
    unsigned long long packed = tagkey | (unsigned)i;          // idx in [0,2^18)
    unsigned slot = ((key * 2654435761u) >> 12) & TMASK;
    unsigned long long cur = g_table[slot];
    while (true) {
        if ((unsigned)(cur >> 44) != gen) {                    // empty or stale
            unsigned long long old = atomicCAS(&g_table[slot], cur, packed);
            if (old == cur) {                                  // claimed this cell
                int pos = atomicAdd(&g_count[row], 1);
                if (pos < PAD) {
                    unsigned apos = (row << 7) + (unsigned)pos;
                    g_pos[slot] = apos;
                    g_cw[apos]  = make_uint2(col, __float_as_uint(aw));
                    atomicAdd(&g_deg[row], aw);                // REDG (no return)
                }
                return;
            }
            cur = old;                                         // re-check same slot
            continue;
        }
        if ((cur >> 18) == (tagkey >> 18)) {                   // same gen+key: dup
            atomicMax(&g_table[slot], packed);
            int p = atomicAdd(&g_nlist, 1);
            if (p < LISTCAP) g_list[p] = make_uint2(slot, (unsigned)i);
            return;
        }
        slot = (slot + 1u) & TMASK;                            // collision: probe
        cur = g_table[slot];
    }
}

// Apply last-write-wins corrections for duplicate cells (few hundred entries).
__global__ void k_fix(const float* __restrict__ ew,
                      const float* __restrict__ adw) {
    int idx = blockIdx.x * blockDim.x + threadIdx.x;
    int n = g_nlist; if (n > LISTCAP) n = LISTCAP;
    if (idx >= n) return;
    unsigned slot = g_list[idx].x;
    unsigned i    = g_list[idx].y;
    unsigned long long cur = g_table[slot];
    if ((unsigned)(cur & 0x3FFFFu) != i) return;               // not the winner
    unsigned apos = g_pos[slot];
    float sig = 1.f / (1.f + expf(-adw[0]));
    float aw  = ew[i] * sig;
    float old = __uint_as_float(g_cw[apos].y);
    g_cw[apos].y = __float_as_uint(aw);
    atomicAdd(&g_deg[apos >> 7], aw - old);
}

// SpMM core: warp per row, edge-exact count, smem-staged edge list, LDS.64
// broadcast (R11 form — best measured). unroll 4 = 4 outstanding gathers.
// SCALE (spmm1): dinv[col] folded during staging; written back for spmm2.
template <bool SCALE>
__device__ __forceinline__ void spmm_gather(const float2* __restrict__ X2,
                                            uint2* __restrict__ srow,
                                            int gw, int lane, int cnt,
                                            float& axo, float& ayo) {
    int base = gw << 7;
    for (int j = lane; j < cnt; j += 32) {                     // coalesced stage
        uint2 cw = g_cw[base + j];
        if (SCALE) {
            float w = __uint_as_float(cw.y) * rsqrtf(g_deg[cw.x] + 1.0f);
            cw.y = __float_as_uint(w);
            g_cw[base + j] = cw;                               // persist for spmm2
        }
        srow[j] = cw;
    }
    __syncwarp();

    float ax = 0.f, ay = 0.f;
#pragma unroll 4
    for (int t = 0; t < cnt; t++) {
        uint2 e = srow[t];                                     // LDS.64 broadcast
        float w = __uint_as_float(e.y);
        float2 xv = X2[e.x * 32 + lane];
        ax = fmaf(w, xv.x, ax);
        ay = fmaf(w, xv.y, ay);
    }
    axo = ax; ayo = ay;
}

__global__ void k_spmm1(const float2* __restrict__ X2) {       // g_tx1 = L x
    __shared__ uint2 s_edges[8][PAD];                          // 8 KB
    int gw = (blockIdx.x * blockDim.x + threadIdx.x) >> 5;
    if (gw >= NN) return;
    int lane = threadIdx.x & 31;
    int cnt = g_count[gw]; if (cnt > PAD) cnt = PAD;
    float ax, ay;
    spmm_gather<true>(X2, s_edges[(threadIdx.x >> 5) & 7], gw, lane, cnt, ax, ay);
    float di = rsqrtf(g_deg[gw] + 1.0f);
    float2 xs = X2[gw * 32 + lane];
    g_tx1[gw * 32 + lane] = make_float2(xs.x - di * (ax + di * xs.x),
                                        xs.y - di * (ay + di * xs.y));
}

// spmm2 fused with the epilogue GEMM, plus next-run state reset:
//  - out[row] = x*W0 + Tx1*W1 + (2*LTx1 - x)*W2 + bias (W via uniform LDG,
//    L1-resident; no extra smem)
//  - each warp zeroes its own g_count/g_deg after last use; one thread resets
//    g_nlist and bumps g_gen (skipping 0 on 20-bit wrap)
__global__ void k_spmm2_out(const float2* __restrict__ X2,
                            const float* __restrict__ W,
                            const float* __restrict__ bias,
                            float2* __restrict__ O2) {
    __shared__ uint2 s_edges[8][PAD];                          // 8 KB
    int gw = (blockIdx.x * blockDim.x + threadIdx.x) >> 5;
    if (gw >= NN) return;
    int lane = threadIdx.x & 31;
    int cnt = g_count[gw]; if (cnt > PAD) cnt = PAD;
    float ax, ay;
    spmm_gather<false>(g_tx1, s_edges[(threadIdx.x >> 5) & 7], gw, lane, cnt, ax, ay);

    float di = rsqrtf(g_deg[gw] + 1.0f);
    float2 t1 = g_tx1[gw * 32 + lane];
    float2 lv;                                                 // LTx1 row
    lv.x = t1.x - di * (ax + di * t1.x);
    lv.y = t1.y - di * (ay + di * t1.y);
    float2 xv = X2[gw * 32 + lane];
    float2 t2;                                                 // Tx2 row
    t2.x = 2.f * lv.x - xv.x;
    t2.y = 2.f * lv.y - xv.y;

    // State reset for the next run (all reads of these fields are done).
    if (lane == 0) { g_count[gw] = 0; g_deg[gw] = 0.f; }
    if (gw == 0 && lane == 0) {
        g_nlist = 0;
        unsigned g = g_gen + 1u;
        if (g > GENMAX) g = 1u;
        g_gen = g;
    }

    const float2* __restrict__ W2 = (const float2*)W;
    float accx = 0.f, accy = 0.f;
#pragma unroll 8
    for (int kp = 0; kp < 32; kp++) {
        int k0 = 2 * kp, k1 = 2 * kp + 1;
        float bx0 = __shfl_sync(0xffffffffu, xv.x, kp);
        float bx1 = __shfl_sync(0xffffffffu, xv.y, kp);
        float b10 = __shfl_sync(0xffffffffu, t1.x, kp);
        float b11 = __shfl_sync(0xffffffffu, t1.y, kp);
        float b20 = __shfl_sync(0xffffffffu, t2.x, kp);
        float b21 = __shfl_sync(0xffffffffu, t2.y, kp);
        float2 w00 = W2[k0 * 32 + lane],        w01 = W2[k1 * 32 + lane];
        float2 w10 = W2[2048 + k0 * 32 + lane], w11 = W2[2048 + k1 * 32 + lane];
        float2 w20 = W2[4096 + k0 * 32 + lane], w21 = W2[4096 + k1 * 32 + lane];
        accx = fmaf(bx0, w00.x, accx); accx = fmaf(bx1, w01.x, accx);
        accx = fmaf(b10, w10.x, accx); accx = fmaf(b11, w11.x, accx);
        accx = fmaf(b20, w20.x, accx); accx = fmaf(b21, w21.x, accx);
        accy = fmaf(bx0, w00.y, accy); accy = fmaf(bx1, w01.y, accy);
        accy = fmaf(b10, w10.y, accy); accy = fmaf(b11, w11.y, accy);
        accy = fmaf(b20, w20.y, accy); accy = fmaf(b21, w21.y, accy);
    }
    float2 b2 = ((const float2*)bias)[lane];
    O2[gw * 32 + lane] = make_float2(accx + b2.x, accy + b2.y);
}

// ---------------- launch -----------------------------------------------------

extern "C" void kernel_launch(void* const* d_in, const int* in_sizes, int n_in,
                              void* d_out, int out_size) {
    const float*    x    = (const float*)d_in[0];
    const unsigned* ei   = (const unsigned*)d_in[1];   // int32 OR int64 raw words
    const float*    ew   = (const float*)d_in[2];      // (E,)
    const float*    W    = (const float*)d_in[3];      // (3, 64, 64)
    const float*    adw  = (const float*)d_in[4];      // (1,)
    const float*    bias = (const float*)d_in[5];      // (64,)
    float*          out  = (float*)d_out;

    int E = in_sizes[2];
    if (E > EMAX) E = EMAX;   // fixed problem; defensive only
    int eb = (E + 255) / 256;

    k_insert   <<<eb, 256>>>(ei, ew, adw, E);
    k_fix      <<<LISTCAP / 256, 256>>>(ew, adw);
    k_spmm1    <<<NN * 32 / 256, 256>>>((const float2*)x);
    k_spmm2_out<<<NN * 32 / 256, 256>>>((const float2*)x, W, bias, (float2*)out);
}

// round 14
// speedup vs baseline: 1.3206x; 1.3206x over previous
#include <cuda_runtime.h>
#include <stdint.h>
#include <math.h>

// Problem constants (fixed by the dataset).
#define NN      8192
#define CC      64
#define EMAX    262144
#define PAD     128                 // padded CSR row stride (mean deg 32)
#define TS      (1u << 19)          // hash slots (load factor ~0.5)
#define TMASK   (TS - 1u)
#define LISTCAP 16384

// Fused kernel smem layout (dynamic): W | edge stage | lv rows
#define SW_BYTES   (3 * 64 * 32 * 8)            // 49152: 6144 float2
#define SE_BYTES   (16 * PAD * 8)               // 16384: 16 warps x 128 uint2
#define SLV_BYTES  (16 * 32 * 8)                //  4096: 16 rows x 32 float2
#define FUSED_SMEM (SW_BYTES + SE_BYTES + SLV_BYTES)   // 69632

// ---------------- scratch (static device globals; no allocation) -------------
__device__ __align__(16) unsigned long long g_table[TS];   // 4 MB dedupe hash
__device__ int      g_is64;
__device__ int      g_count[NN];          // distinct cells per row
__device__ float    g_deg[NN];
__device__ unsigned g_pos[TS];            // apos recorded by the claimant of a slot
__device__ __align__(16) uint2 g_cw[NN * PAD];   // 8 MB interleaved (col, w)
__device__ float2   g_tx1[NN * 32];
__device__ int      g_nlist;
__device__ uint2    g_list[LISTCAP];      // (slot, edge idx) of duplicate-key inserts

// ---------------- kernels ----------------------------------------------------

// Clear table (16B stores) + counters; detect int32 vs int64 edge storage.
__global__ void k_clear(const unsigned* __restrict__ ei) {
    unsigned i = blockIdx.x * blockDim.x + threadIdx.x;       // 262144 threads
    ((ulonglong2*)g_table)[i] = make_ulonglong2(0ull, 0ull);  // 2 slots each
    if (i < NN) { g_count[i] = 0; g_deg[i] = 0.f; }
    if (i == 0) {
        g_nlist = 0;
        int all_zero = 1;
        for (int j = 1; j < 64; j += 2) all_zero &= (ei[j] == 0u);
        g_is64 = all_zero;   // int64 LE with values<2^31 => odd words zero
    }
}

// Insert: claimant of a cell takes a padded-CSR position and writes (col,w) +
// REDG degree. Duplicate-key edges go to a tiny fix list. atomicMax on
// (key+1)<<32|(i+1) keeps the highest edge idx = last-write-wins.
__global__ void k_insert(const unsigned* __restrict__ ei,
                         const float* __restrict__ ew,
                         const float* __restrict__ adw, int E) {
    int i = blockIdx.x * blockDim.x + threadIdx.x;
    if (i >= E) return;
    unsigned row, col;
    if (g_is64) {                                 // coalesced 8B loads
        row = ((const uint2*)ei)[i].x;
        col = ((const uint2*)ei)[E + i].x;
    } else {
        row = ei[i];
        col = ei[E + i];
    }
    float sig = 1.f / (1.f + expf(-adw[0]));
    float aw  = ew[i] * sig;
    unsigned key = (row << 13) | col;                         // < 2^26
    unsigned long long packed =
        ((unsigned long long)(key + 1u) << 32) | (unsigned)(i + 1);
    unsigned slot = ((key * 2654435761u) >> 12) & TMASK;
    while (true) {
        unsigned long long cur = g_table[slot];
        if (cur == 0ull) {
            unsigned long long old = atomicCAS(&g_table[slot], 0ull, packed);
            if (old == 0ull) {                                 // claimed this cell
                int pos = atomicAdd(&g_count[row], 1);
                if (pos < PAD) {
                    unsigned apos = (row << 7) + (unsigned)pos;
                    g_pos[slot] = apos;
                    g_cw[apos]  = make_uint2(col, __float_as_uint(aw));
                    atomicAdd(&g_deg[row], aw);                // REDG (no return)
                }
                return;
            }
            cur = old;
        }
        if ((cur >> 32) == (unsigned long long)(key + 1u)) {   // duplicate cell
            atomicMax(&g_table[slot], packed);
            int p = atomicAdd(&g_nlist, 1);
            if (p < LISTCAP) g_list[p] = make_uint2(slot, (unsigned)i);
            return;
        }
        slot = (slot + 1u) & TMASK;
    }
}

// Apply last-write-wins corrections for duplicate cells (few hundred entries).
__global__ void k_fix(const float* __restrict__ ew,
                      const float* __restrict__ adw) {
    int idx = blockIdx.x * blockDim.x + threadIdx.x;
    int n = g_nlist; if (n > LISTCAP) n = LISTCAP;
    if (idx >= n) return;
    unsigned slot = g_list[idx].x;
    unsigned i    = g_list[idx].y;
    unsigned long long cur = g_table[slot];
    if ((unsigned)cur != i + 1u) return;                       // not the winner
    unsigned apos = g_pos[slot];
    float sig = 1.f / (1.f + expf(-adw[0]));
    float aw  = ew[i] * sig;
    float old = __uint_as_float(g_cw[apos].y);
    g_cw[apos].y = __float_as_uint(aw);
    atomicAdd(&g_deg[apos >> 7], aw - old);
}

// SpMM core (R11 form, best measured): warp per row, edge-exact count,
// smem-staged edge list, LDS.64 broadcast, unroll 4.
// SCALE (spmm1): dinv[col] folded during staging; written back for spmm2.
template <bool SCALE>
__device__ __forceinline__ void spmm_gather(const float2* __restrict__ X2,
                                            uint2* __restrict__ srow,
                                            int gw, int lane, int cnt,
                                            float& axo, float& ayo) {
    int base = gw << 7;
    for (int j = lane; j < cnt; j += 32) {                     // coalesced stage
        uint2 cw = g_cw[base + j];
        if (SCALE) {
            float w = __uint_as_float(cw.y) * rsqrtf(g_deg[cw.x] + 1.0f);
            cw.y = __float_as_uint(w);
            g_cw[base + j] = cw;                               // persist for spmm2
        }
        srow[j] = cw;
    }
    __syncwarp();

    float ax = 0.f, ay = 0.f;
#pragma unroll 4
    for (int t = 0; t < cnt; t++) {
        uint2 e = srow[t];                                     // LDS.64 broadcast
        float w = __uint_as_float(e.y);
        float2 xv = X2[e.x * 32 + lane];
        ax = fmaf(w, xv.x, ax);
        ay = fmaf(w, xv.y, ay);
    }
    axo = ax; ayo = ay;
}

__global__ void k_spmm1(const float2* __restrict__ X2) {       // g_tx1 = L x
    __shared__ uint2 s_edges[8][PAD];                          // 8 KB
    int gw = (blockIdx.x * blockDim.x + threadIdx.x) >> 5;
    if (gw >= NN) return;
    int lane = threadIdx.x & 31;
    int cnt = g_count[gw]; if (cnt > PAD) cnt = PAD;
    float ax, ay;
    spmm_gather<true>(X2, s_edges[(threadIdx.x >> 5) & 7], gw, lane, cnt, ax, ay);
    float di = rsqrtf(g_deg[gw] + 1.0f);
    float2 xs = X2[gw * 32 + lane];
    g_tx1[gw * 32 + lane] = make_float2(xs.x - di * (ax + di * xs.x),
                                        xs.y - di * (ay + di * xs.y));
}

// Fused spmm2 + epilogue. 512 threads = 16 row-warps per block.
// Phase A: cooperative W -> smem (latency hidden under gather).
// Phase B: per-warp gather (R11 loop) -> lv row -> smem.
// Phase C: warps 0-3 run the R11 k_out GEMM (4 rows/warp, smem W, smem lv;
//          xv/t1 re-read from L2 exactly as R11's k_out did).
__global__ void k_spmm2_out(const float2* __restrict__ X2,
                            const float* __restrict__ W,
                            const float* __restrict__ bias,
                            float2* __restrict__ O2) {
    extern __shared__ char smem[];
    float2* sW  = (float2*)smem;                               // 6144 float2
    uint2*  sE  = (uint2*)(smem + SW_BYTES);                   // 16 x 128 uint2
    float2* sLv = (float2*)(smem + SW_BYTES + SE_BYTES);       // 16 x 32 float2

    int wib  = threadIdx.x >> 5;                               // 0..15
    int lane = threadIdx.x & 31;
    int gw   = blockIdx.x * 16 + wib;                          // row (grid exact)

    // Phase A: W -> smem (coalesced; consumed only after __syncthreads)
    const float2* __restrict__ Wg = (const float2*)W;
    for (int j = threadIdx.x; j < 3 * 64 * 32; j += 512) sW[j] = Wg[j];

    // Phase B: gather LTx1 row
    int cnt = g_count[gw]; if (cnt > PAD) cnt = PAD;
    float ax, ay;
    spmm_gather<false>(g_tx1, sE + wib * PAD, gw, lane, cnt, ax, ay);
    float di = rsqrtf(g_deg[gw] + 1.0f);
    float2 t1v = g_tx1[gw * 32 + lane];
    sLv[wib * 32 + lane] = make_float2(t1v.x - di * (ax + di * t1v.x),
                                       t1v.y - di * (ay + di * t1v.y));
    __syncthreads();

    // Phase C: GEMM, warps 0-3, 4 rows each (R11 k_out body)
    if (wib < 4) {
        int row0 = blockIdx.x * 16 + wib * 4;
        float2 xv[4], t1[4], t2[4], acc[4];
#pragma unroll
        for (int r = 0; r < 4; r++) {
            int row = row0 + r;
            xv[r] = X2[row * 32 + lane];
            t1[r] = g_tx1[row * 32 + lane];
            float2 lv = sLv[(wib * 4 + r) * 32 + lane];
            t2[r].x = 2.f * lv.x - xv[r].x;
            t2[r].y = 2.f * lv.y - xv[r].y;
            acc[r].x = 0.f; acc[r].y = 0.f;
        }
#pragma unroll 8
        for (int kp = 0; kp < 32; kp++) {
            int k0 = 2 * kp, k1 = 2 * kp + 1;
            float2 w00 = sW[k0 * 32 + lane],        w01 = sW[k1 * 32 + lane];
            float2 w10 = sW[2048 + k0 * 32 + lane], w11 = sW[2048 + k1 * 32 + lane];
            float2 w20 = sW[4096 + k0 * 32 + lane], w21 = sW[4096 + k1 * 32 + lane];
#pragma unroll
            for (int r = 0; r < 4; r++) {
                float bx0 = __shfl_sync(0xffffffffu, xv[r].x, kp);
                float bx1 = __shfl_sync(0xffffffffu, xv[r].y, kp);
                float b10 = __shfl_sync(0xffffffffu, t1[r].x, kp);
                float b11 = __shfl_sync(0xffffffffu, t1[r].y, kp);
                float b20 = __shfl_sync(0xffffffffu, t2[r].x, kp);
                float b21 = __shfl_sync(0xffffffffu, t2[r].y, kp);
                acc[r].x = fmaf(bx0, w00.x, acc[r].x); acc[r].x = fmaf(bx1, w01.x, acc[r].x);
                acc[r].x = fmaf(b10, w10.x, acc[r].x); acc[r].x = fmaf(b11, w11.x, acc[r].x);
                acc[r].x = fmaf(b20, w20.x, acc[r].x); acc[r].x = fmaf(b21, w21.x, acc[r].x);
                acc[r].y = fmaf(bx0, w00.y, acc[r].y); acc[r].y = fmaf(bx1, w01.y, acc[r].y);
                acc[r].y = fmaf(b10, w10.y, acc[r].y); acc[r].y = fmaf(b11, w11.y, acc[r].y);
                acc[r].y = fmaf(b20, w20.y, acc[r].y); acc[r].y = fmaf(b21, w21.y, acc[r].y);
            }
        }
        float2 b2 = ((const float2*)bias)[lane];
#pragma unroll
        for (int r = 0; r < 4; r++)
            O2[(row0 + r) * 32 + lane] = make_float2(acc[r].x + b2.x,
                                                     acc[r].y + b2.y);
    }
}

// ---------------- launch -----------------------------------------------------

extern "C" void kernel_launch(void* const* d_in, const int* in_sizes, int n_in,
                              void* d_out, int out_size) {
    const float*    x    = (const float*)d_in[0];
    const unsigned* ei   = (const unsigned*)d_in[1];   // int32 OR int64 raw words
    const float*    ew   = (const float*)d_in[2];      // (E,)
    const float*    W    = (const float*)d_in[3];      // (3, 64, 64)
    const float*    adw  = (const float*)d_in[4];      // (1,)
    const float*    bias = (const float*)d_in[5];      // (64,)
    float*          out  = (float*)d_out;

    int E = in_sizes[2];
    if (E > EMAX) E = EMAX;   // fixed problem; defensive only
    int eb = (E + 255) / 256;

    cudaFuncSetAttribute(k_spmm2_out,
                         cudaFuncAttributeMaxDynamicSharedMemorySize, FUSED_SMEM);

    k_clear    <<<TS / 2 / 256, 256>>>(ei);            // 1024 blocks
    k_insert   <<<eb, 256>>>(ei, ew, adw, E);
    k_fix      <<<LISTCAP / 256, 256>>>(ew, adw);
    k_spmm1    <<<NN * 32 / 256, 256>>>((const float2*)x);
    k_spmm2_out<<<NN / 16, 512, FUSED_SMEM>>>((const float2*)x, W, bias,
                                              (float2*)out);
}

// round 15
// speedup vs baseline: 1.4941x; 1.1314x over previous
#include <cuda_runtime.h>
#include <stdint.h>
#include <math.h>

// Problem constants (fixed by the dataset).
#define NN      8192
#define CC      64
#define EMAX    262144
#define PAD     128                 // padded CSR row stride (mean deg 32)
#define TS      (1u << 19)          // hash slots (load factor ~0.5)
#define TMASK   (TS - 1u)
#define LISTCAP 16384

// ---------------- scratch (static device globals; no allocation) -------------
__device__ __align__(16) unsigned long long g_table[TS];   // 4 MB dedupe hash
__device__ int      g_is64;
__device__ int      g_count[NN];          // distinct cells per row
__device__ float    g_deg[NN];
__device__ unsigned g_pos[TS];            // apos recorded by the claimant of a slot
__device__ __align__(16) uint2 g_cw[NN * PAD];   // 8 MB interleaved (col, w)
__device__ float2   g_tx1[NN * 32];
__device__ float2   g_ltx1[NN * 32];
__device__ int      g_nlist;
__device__ uint2    g_list[LISTCAP];      // (slot, edge idx) of duplicate-key inserts

// ---------------- kernels ----------------------------------------------------

// Clear table (16B stores) + counters; detect int32 vs int64 edge storage.
__global__ void k_clear(const unsigned* __restrict__ ei) {
    unsigned i = blockIdx.x * blockDim.x + threadIdx.x;       // 262144 threads
    ((ulonglong2*)g_table)[i] = make_ulonglong2(0ull, 0ull);  // 2 slots each
    if (i < NN) { g_count[i] = 0; g_deg[i] = 0.f; }
    if (i == 0) {
        g_nlist = 0;
        int all_zero = 1;
        for (int j = 1; j < 64; j += 2) all_zero &= (ei[j] == 0u);
        g_is64 = all_zero;   // int64 LE with values<2^31 => odd words zero
    }
}

// Insert: claimant of a cell takes a padded-CSR position and writes (col,w) +
// REDG degree. Duplicate-key edges go to a tiny fix list. atomicMax on
// (key+1)<<32|(i+1) keeps the highest edge idx = last-write-wins.
__global__ void k_insert(const unsigned* __restrict__ ei,
                         const float* __restrict__ ew,
                         const float* __restrict__ adw, int E) {
    int i = blockIdx.x * blockDim.x + threadIdx.x;
    if (i >= E) return;
    unsigned row, col;
    if (g_is64) {                                 // coalesced 8B loads
        row = ((const uint2*)ei)[i].x;
        col = ((const uint2*)ei)[E + i].x;
    } else {
        row = ei[i];
        col = ei[E + i];
    }
    float sig = 1.f / (1.f + expf(-adw[0]));
    float aw  = ew[i] * sig;
    unsigned key = (row << 13) | col;                         // < 2^26
    unsigned long long packed =
        ((unsigned long long)(key + 1u) << 32) | (unsigned)(i + 1);
    unsigned slot = ((key * 2654435761u) >> 12) & TMASK;
    while (true) {
        unsigned long long cur = g_table[slot];
        if (cur == 0ull) {
            unsigned long long old = atomicCAS(&g_table[slot], 0ull, packed);
            if (old == 0ull) {                                 // claimed this cell
                int pos = atomicAdd(&g_count[row], 1);
                if (pos < PAD) {
                    unsigned apos = (row << 7) + (unsigned)pos;
                    g_pos[slot] = apos;
                    g_cw[apos]  = make_uint2(col, __float_as_uint(aw));
                    atomicAdd(&g_deg[row], aw);                // REDG (no return)
                }
                return;
            }
            cur = old;
        }
        if ((cur >> 32) == (unsigned long long)(key + 1u)) {   // duplicate cell
            atomicMax(&g_table[slot], packed);
            int p = atomicAdd(&g_nlist, 1);
            if (p < LISTCAP) g_list[p] = make_uint2(slot, (unsigned)i);
            return;
        }
        slot = (slot + 1u) & TMASK;
    }
}

// Apply last-write-wins corrections for duplicate cells (few hundred entries).
__global__ void k_fix(const float* __restrict__ ew,
                      const float* __restrict__ adw) {
    int idx = blockIdx.x * blockDim.x + threadIdx.x;
    int n = g_nlist; if (n > LISTCAP) n = LISTCAP;
    if (idx >= n) return;
    unsigned slot = g_list[idx].x;
    unsigned i    = g_list[idx].y;
    unsigned long long cur = g_table[slot];
    if ((unsigned)cur != i + 1u) return;                       // not the winner
    unsigned apos = g_pos[slot];
    float sig = 1.f / (1.f + expf(-adw[0]));
    float aw  = ew[i] * sig;
    float old = __uint_as_float(g_cw[apos].y);
    g_cw[apos].y = __float_as_uint(aw);
    atomicAdd(&g_deg[apos >> 7], aw - old);
}

// SpMM core (R11 form): warp per row, edge-exact count, smem-staged edge
// list, LDS.64 broadcast. unroll 8 (was 4) -> more gathers in flight.
// SCALE (spmm1): dinv[col] folded during staging; written back for spmm2.
template <bool SCALE>
__device__ __forceinline__ void spmm_gather(const float2* __restrict__ X2,
                                            uint2* __restrict__ srow,
                                            int gw, int lane, int cnt,
                                            float& axo, float& ayo) {
    int base = gw << 7;
    for (int j = lane; j < cnt; j += 32) {                     // coalesced stage
        uint2 cw = g_cw[base + j];
        if (SCALE) {
            float w = __uint_as_float(cw.y) * rsqrtf(g_deg[cw.x] + 1.0f);
            cw.y = __float_as_uint(w);
            g_cw[base + j] = cw;                               // persist for spmm2
        }
        srow[j] = cw;
    }
    __syncwarp();

    float ax = 0.f, ay = 0.f;
#pragma unroll 8
    for (int t = 0; t < cnt; t++) {
        uint2 e = srow[t];                                     // LDS.64 broadcast
        float w = __uint_as_float(e.y);
        float2 xv = X2[e.x * 32 + lane];
        ax = fmaf(w, xv.x, ax);
        ay = fmaf(w, xv.y, ay);
    }
    axo = ax; ayo = ay;
}

__global__ void k_spmm1(const float2* __restrict__ X2) {       // g_tx1 = L x
    __shared__ uint2 s_edges[8][PAD];                          // 8 KB
    int gw = (blockIdx.x * blockDim.x + threadIdx.x) >> 5;
    if (gw >= NN) return;
    int lane = threadIdx.x & 31;
    int cnt = g_count[gw]; if (cnt > PAD) cnt = PAD;
    float ax, ay;
    spmm_gather<true>(X2, s_edges[(threadIdx.x >> 5) & 7], gw, lane, cnt, ax, ay);
    float di = rsqrtf(g_deg[gw] + 1.0f);
    float2 xs = X2[gw * 32 + lane];
    g_tx1[gw * 32 + lane] = make_float2(xs.x - di * (ax + di * xs.x),
                                        xs.y - di * (ay + di * xs.y));
}

__global__ void k_spmm2() {                                    // g_ltx1 = L Tx1
    __shared__ uint2 s_edges[8][PAD];                          // 8 KB
    int gw = (blockIdx.x * blockDim.x + threadIdx.x) >> 5;
    if (gw >= NN) return;
    int lane = threadIdx.x & 31;
    int cnt = g_count[gw]; if (cnt > PAD) cnt = PAD;
    float ax, ay;
    spmm_gather<false>(g_tx1, s_edges[(threadIdx.x >> 5) & 7], gw, lane, cnt, ax, ay);
    float di = rsqrtf(g_deg[gw] + 1.0f);
    float2 t1 = g_tx1[gw * 32 + lane];
    g_ltx1[gw * 32 + lane] = make_float2(t1.x - di * (ax + di * t1.x),
                                         t1.y - di * (ay + di * t1.y));
}

// out = x*W0 + Tx1*W1 + (2*LTx1 - x)*W2 + bias. 4 rows/warp, W in smem.
__global__ void k_out(const float* __restrict__ x,
                      const float* __restrict__ W,
                      const float* __restrict__ bias,
                      float* __restrict__ out) {
    __shared__ float2 sW[3 * 64 * 32];                         // 48 KB
    const float2* __restrict__ W2 = (const float2*)W;
    for (int j = threadIdx.x; j < 3 * 64 * 32; j += blockDim.x) sW[j] = W2[j];
    __syncthreads();

    int warp = threadIdx.x >> 5;
    int lane = threadIdx.x & 31;
    int row0 = blockIdx.x * 32 + warp * 4;

    const float2* __restrict__ X2 = (const float2*)x;
    float2* __restrict__ O2 = (float2*)out;

    float2 xv[4], t1[4], t2[4], acc[4];
#pragma unroll
    for (int r = 0; r < 4; r++) {
        int row = row0 + r;
        xv[r] = X2[row * 32 + lane];
        t1[r] = g_tx1[row * 32 + lane];
        float2 lv = g_ltx1[row * 32 + lane];
        t2[r].x = 2.f * lv.x - xv[r].x;
        t2[r].y = 2.f * lv.y - xv[r].y;
        acc[r].x = 0.f; acc[r].y = 0.f;
    }

#pragma unroll 8
    for (int kp = 0; kp < 32; kp++) {
        int k0 = 2 * kp, k1 = 2 * kp + 1;
        float2 w00 = sW[k0 * 32 + lane],        w01 = sW[k1 * 32 + lane];
        float2 w10 = sW[2048 + k0 * 32 + lane], w11 = sW[2048 + k1 * 32 + lane];
        float2 w20 = sW[4096 + k0 * 32 + lane], w21 = sW[4096 + k1 * 32 + lane];
#pragma unroll
        for (int r = 0; r < 4; r++) {
            float bx0 = __shfl_sync(0xffffffffu, xv[r].x, kp);
            float bx1 = __shfl_sync(0xffffffffu, xv[r].y, kp);
            float b10 = __shfl_sync(0xffffffffu, t1[r].x, kp);
            float b11 = __shfl_sync(0xffffffffu, t1[r].y, kp);
            float b20 = __shfl_sync(0xffffffffu, t2[r].x, kp);
            float b21 = __shfl_sync(0xffffffffu, t2[r].y, kp);
            acc[r].x = fmaf(bx0, w00.x, acc[r].x); acc[r].x = fmaf(bx1, w01.x, acc[r].x);
            acc[r].x = fmaf(b10, w10.x, acc[r].x); acc[r].x = fmaf(b11, w11.x, acc[r].x);
            acc[r].x = fmaf(b20, w20.x, acc[r].x); acc[r].x = fmaf(b21, w21.x, acc[r].x);
            acc[r].y = fmaf(bx0, w00.y, acc[r].y); acc[r].y = fmaf(bx1, w01.y, acc[r].y);
            acc[r].y = fmaf(b10, w10.y, acc[r].y); acc[r].y = fmaf(b11, w11.y, acc[r].y);
            acc[r].y = fmaf(b20, w20.y, acc[r].y); acc[r].y = fmaf(b21, w21.y, acc[r].y);
        }
    }

    float2 b2 = ((const float2*)bias)[lane];
#pragma unroll
    for (int r = 0; r < 4; r++) {
        float2 o; o.x = acc[r].x + b2.x; o.y = acc[r].y + b2.y;
        O2[(row0 + r) * 32 + lane] = o;
    }
}

// ---------------- launch -----------------------------------------------------

extern "C" void kernel_launch(void* const* d_in, const int* in_sizes, int n_in,
                              void* d_out, int out_size) {
    const float*    x    = (const float*)d_in[0];
    const unsigned* ei   = (const unsigned*)d_in[1];   // int32 OR int64 raw words
    const float*    ew   = (const float*)d_in[2];      // (E,)
    const float*    W    = (const float*)d_in[3];      // (3, 64, 64)
    const float*    adw  = (const float*)d_in[4];      // (1,)
    const float*    bias = (const float*)d_in[5];      // (64,)
    float*          out  = (float*)d_out;

    int E = in_sizes[2];
    if (E > EMAX) E = EMAX;   // fixed problem; defensive only
    int eb = (E + 255) / 256;

    k_clear <<<TS / 2 / 256, 256>>>(ei);               // 1024 blocks
    k_insert<<<eb, 256>>>(ei, ew, adw, E);
    k_fix   <<<LISTCAP / 256, 256>>>(ew, adw);
    k_spmm1 <<<NN * 32 / 256, 256>>>((const float2*)x); // Tx1 = L x (+ scale fold)
    k_spmm2 <<<NN * 32 / 256, 256>>>();                 // LTx1 = L Tx1
    k_out   <<<NN / 32, 256>>>(x, W, bias, out);
}